// round 10
// baseline (speedup 1.0000x reference)
#include <cuda_runtime.h>

// ---------------------------------------------------------------------------
// GIN layer:  agg = segment_max(feats[src], dst) (empty -> 0)
//             h   = feats + agg
//             h1  = relu(BN(h @ W1 + b1))
//             h2  = relu(BN(h1 @ W2 + b2))
//             out = BN(h2)
// R10: fma.rn.f32x2 packed GEMM; finalize fused into producers via
//      threadfence+ticket last-block combine (6 launches total).
// ---------------------------------------------------------------------------

#define N_NODES 50000
#define N_EDGES 800000
#define D 128
#define CAP 128
#define BN_EPS 1e-5f
#define NBLK_GEMM 391          // ceil(50000 / 128)
#define NBLK_RED 128           // colreduce blocks (391 rows each)

typedef unsigned long long u64;

// ----------------------------- scratch (static, no allocs) -----------------
__device__ int   d_cnt[N_NODES];                 // zero-init; re-zeroed each run
__device__ int   d_bucket[N_NODES * CAP];
__device__ float d_H [N_NODES * D];
__device__ float d_Y1[N_NODES * D];
__device__ float d_Y2[N_NODES * D];
__device__ float d_psum[NBLK_GEMM * D];
__device__ float d_psq [NBLK_GEMM * D];
__device__ int   d_ticket[4];                    // per-kernel arrival counters
__device__ float d_scale1[D], d_shift1[D];
__device__ float d_scale2[D], d_shift2[D];
__device__ float d_scale3[D], d_shift3[D];

// ----------------------------- f32x2 helpers -------------------------------
__device__ __forceinline__ u64 pack2(float x, float y) {
    u64 r;
    asm("mov.b64 %0, {%1, %2};" : "=l"(r)
        : "r"(__float_as_uint(x)), "r"(__float_as_uint(y)));
    return r;
}
__device__ __forceinline__ u64 fma2(u64 a, u64 b, u64 c) {
    u64 d;
    asm("fma.rn.f32x2 %0, %1, %2, %3;" : "=l"(d) : "l"(a), "l"(b), "l"(c));
    return d;
}
__device__ __forceinline__ float2 unpack2(u64 p) {
    unsigned lo, hi;
    asm("mov.b64 {%0, %1}, %2;" : "=r"(lo), "=r"(hi) : "l"(p));
    return make_float2(__uint_as_float(lo), __uint_as_float(hi));
}

// ----------------------------- K1: scatter edges into dst buckets ----------
__global__ void scatter_kernel(const int* __restrict__ src,
                               const int* __restrict__ dst) {
    int e = blockIdx.x * blockDim.x + threadIdx.x;
    if (e >= N_EDGES) return;
    int dn = dst[e], sn = src[e];
    int p = atomicAdd(&d_cnt[dn], 1);
    if (p < CAP) d_bucket[dn * CAP + p] = sn;
    // overflow: aggregate_kernel rescans all edges for that node
}

// ----------------------------- K2: warp-per-node max aggregation -----------
__global__ void aggregate_kernel(const float* __restrict__ feats,
                                 const int* __restrict__ src,
                                 const int* __restrict__ dst) {
    int gtid = blockIdx.x * blockDim.x + threadIdx.x;
    int node = gtid >> 5;
    int lane = gtid & 31;
    if (node >= N_NODES) return;
    const float4* f4 = reinterpret_cast<const float4*>(feats);

    int c = d_cnt[node];
    float4 acc = make_float4(-3.402823466e38f, -3.402823466e38f,
                             -3.402823466e38f, -3.402823466e38f);
    if (c <= CAP) {
        const int* bk = d_bucket + node * CAP;
        int e = 0;
        for (; e + 4 <= c; e += 4) {
            int s0 = bk[e+0], s1 = bk[e+1], s2 = bk[e+2], s3 = bk[e+3];
            float4 v0 = f4[s0 * 32 + lane];
            float4 v1 = f4[s1 * 32 + lane];
            float4 v2 = f4[s2 * 32 + lane];
            float4 v3 = f4[s3 * 32 + lane];
            acc.x = fmaxf(acc.x, fmaxf(fmaxf(v0.x, v1.x), fmaxf(v2.x, v3.x)));
            acc.y = fmaxf(acc.y, fmaxf(fmaxf(v0.y, v1.y), fmaxf(v2.y, v3.y)));
            acc.z = fmaxf(acc.z, fmaxf(fmaxf(v0.z, v1.z), fmaxf(v2.z, v3.z)));
            acc.w = fmaxf(acc.w, fmaxf(fmaxf(v0.w, v1.w), fmaxf(v2.w, v3.w)));
        }
        for (; e < c; ++e) {
            int s = bk[e];
            float4 v = f4[s * 32 + lane];
            acc.x = fmaxf(acc.x, v.x); acc.y = fmaxf(acc.y, v.y);
            acc.z = fmaxf(acc.z, v.z); acc.w = fmaxf(acc.w, v.w);
        }
    } else {
        for (int e = 0; e < N_EDGES; ++e) {      // never-path, deterministic
            if (dst[e] == node) {
                float4 v = f4[src[e] * 32 + lane];
                acc.x = fmaxf(acc.x, v.x); acc.y = fmaxf(acc.y, v.y);
                acc.z = fmaxf(acc.z, v.z); acc.w = fmaxf(acc.w, v.w);
            }
        }
    }
    float4 b = f4[node * 32 + lane];
    float4 h;
    if (c == 0) h = b;
    else { h.x = b.x + acc.x; h.y = b.y + acc.y;
           h.z = b.z + acc.z; h.w = b.w + acc.w; }
    reinterpret_cast<float4*>(d_H)[node * 32 + lane] = h;
}

// ------------- fp32 (f32x2-packed) SGEMM + fused BN stats + finalize -------
// 512 threads, tile 128(M) x 128(N) x 128(full K), 8x4 microtile with
// column-paired f32x2 accumulators. Last-arriving block combines partials
// into scale/shift (deterministic fixed-order combine).
__global__ void __launch_bounds__(512)
gemm_kernel(const float* __restrict__ A, const float* __restrict__ Wg,
            const float* __restrict__ bias, float* __restrict__ Y,
            const float* __restrict__ ts, const float* __restrict__ tt,
            const float* __restrict__ g, const float* __restrict__ be,
            float* __restrict__ scale, float* __restrict__ shift,
            int slot) {
    extern __shared__ float smem[];
    float* As = smem;             // [128][128] (m, k)
    float* Ws = smem + 128 * 128; // [128][128] (k, n)
    __shared__ int s_last;

    const int tid  = threadIdx.x;
    const int tcol = tid & 31;    // cols tcol*4 .. +3
    const int trow = tid >> 5;    // rows trow*8 .. +7
    const int block_row = blockIdx.x * 128;

    const float4* A4 = reinterpret_cast<const float4*>(A);
    const float4* W4 = reinterpret_cast<const float4*>(Wg);
    float4*       As4 = reinterpret_cast<float4*>(As);
    float4*       Ws4 = reinterpret_cast<float4*>(Ws);

    #pragma unroll
    for (int i = 0; i < 8; ++i) {
        int f4i = tid + i * 512;              // 0..4095
        int m   = f4i >> 5;
        int k4  = f4i & 31;
        int row = block_row + m;
        float4 v = make_float4(0.f, 0.f, 0.f, 0.f);
        if (row < N_NODES) v = A4[row * 32 + k4];
        if (ts) {
            int k = k4 * 4;
            v.x = fmaxf(fmaf(ts[k+0], v.x, tt[k+0]), 0.f);
            v.y = fmaxf(fmaf(ts[k+1], v.y, tt[k+1]), 0.f);
            v.z = fmaxf(fmaf(ts[k+2], v.z, tt[k+2]), 0.f);
            v.w = fmaxf(fmaf(ts[k+3], v.w, tt[k+3]), 0.f);
        }
        As4[f4i] = v;
        Ws4[f4i] = W4[f4i];
    }
    __syncthreads();

    u64 acc2[8][2];
    #pragma unroll
    for (int i = 0; i < 8; ++i) { acc2[i][0] = 0ull; acc2[i][1] = 0ull; }

    #pragma unroll 4
    for (int k = 0; k < 128; ++k) {
        float a[8];
        #pragma unroll
        for (int i = 0; i < 8; ++i) a[i] = As[(trow * 8 + i) * 128 + k];
        // two packed f32x2 B operands straight from the float4 smem slot
        ulonglong2 bp = *reinterpret_cast<const ulonglong2*>(
                            &Ws[k * 128 + tcol * 4]);
        #pragma unroll
        for (int i = 0; i < 8; ++i) {
            u64 ad = pack2(a[i], a[i]);
            acc2[i][0] = fma2(ad, bp.x, acc2[i][0]);
            acc2[i][1] = fma2(ad, bp.y, acc2[i][1]);
        }
    }

    float bb[4];
    #pragma unroll
    for (int j = 0; j < 4; ++j) bb[j] = bias[tcol * 4 + j];

    float cs[4] = {0.f, 0.f, 0.f, 0.f};
    float cq[4] = {0.f, 0.f, 0.f, 0.f};

    #pragma unroll
    for (int i = 0; i < 8; ++i) {
        int row = block_row + trow * 8 + i;
        if (row < N_NODES) {
            float2 p0 = unpack2(acc2[i][0]);
            float2 p1 = unpack2(acc2[i][1]);
            float v[4] = { p0.x + bb[0], p0.y + bb[1],
                           p1.x + bb[2], p1.y + bb[3] };
            #pragma unroll
            for (int j = 0; j < 4; ++j) { cs[j] += v[j]; cq[j] += v[j]*v[j]; }
            *reinterpret_cast<float4*>(Y + row * 128 + tcol * 4) =
                make_float4(v[0], v[1], v[2], v[3]);
        }
    }

    // deterministic per-block column-stat reduction (reuse smem)
    __syncthreads();
    float* ssum = smem;            // [16][128]
    float* ssq  = smem + 2048;     // [16][128]
    #pragma unroll
    for (int j = 0; j < 4; ++j) {
        ssum[trow * 128 + tcol * 4 + j] = cs[j];
        ssq [trow * 128 + tcol * 4 + j] = cq[j];
    }
    __syncthreads();
    if (tid < 128) {
        float s = 0.f, q = 0.f;
        #pragma unroll
        for (int t = 0; t < 16; ++t) {
            s += ssum[t * 128 + tid];
            q += ssq [t * 128 + tid];
        }
        d_psum[blockIdx.x * 128 + tid] = s;
        d_psq [blockIdx.x * 128 + tid] = q;
    }

    // ---- last-block finalize (ticket) ----
    __threadfence();
    __syncthreads();
    if (tid == 0) {
        int old = atomicAdd(&d_ticket[slot], 1);
        s_last = (old == (int)gridDim.x - 1);
        if (s_last) d_ticket[slot] = 0;           // reset for next replay
    }
    __syncthreads();
    if (s_last) {
        __threadfence();
        int c  = tid & 127;
        int sl = tid >> 7;                        // 0..3
        float sm = 0.f, q = 0.f;
        for (int b = sl; b < (int)gridDim.x; b += 4) {  // fixed-order slices
            sm += d_psum[b * 128 + c];
            q  += d_psq [b * 128 + c];
        }
        __syncthreads();                          // smem reuse barrier
        ssum[sl * 128 + c] = sm;
        ssq [sl * 128 + c] = q;
        __syncthreads();
        if (sl == 0) {
            float S = 0.f, Q = 0.f;
            #pragma unroll
            for (int t = 0; t < 4; ++t) {         // fixed order
                S += ssum[t * 128 + c];
                Q += ssq [t * 128 + c];
            }
            float m = S / (float)N_NODES;
            float v = Q / (float)N_NODES - m * m;
            float a = g[c] * rsqrtf(v + BN_EPS);
            scale[c] = a;
            shift[c] = be[c] - m * a;
        }
    }
}

// -------------- colreduce (phase-3 stats) + fused finalize -----------------
// 128 blocks x 256 thr: two row-slices per column, then last-block combine.
__global__ void __launch_bounds__(256)
colreduce_kernel(const float* __restrict__ X,
                 const float* __restrict__ ts, const float* __restrict__ tt,
                 const float* __restrict__ g, const float* __restrict__ be,
                 float* __restrict__ scale, float* __restrict__ shift) {
    __shared__ float s0[128], q0[128];
    __shared__ int s_last;
    const int t  = threadIdx.x;
    const int c  = t & 127;
    const int sl = t >> 7;                        // 0 or 1
    int r0 = blockIdx.x * 391;
    int r1 = r0 + 391; if (r1 > N_NODES) r1 = N_NODES;
    float sc = ts[c], sh = tt[c];
    float sm = 0.f, sq = 0.f;
    for (int r = r0 + sl; r < r1; r += 2) {       // fixed order per slice
        float v = fmaxf(fmaf(sc, X[r * 128 + c], sh), 0.f);
        sm += v; sq += v * v;
    }
    if (sl == 1) { s0[c] = sm; q0[c] = sq; }
    __syncthreads();
    if (sl == 0) {                                // fixed combine order
        sm += s0[c]; sq += q0[c];
        d_psum[blockIdx.x * 128 + c] = sm;
        d_psq [blockIdx.x * 128 + c] = sq;
    }
    __threadfence();
    __syncthreads();
    if (t == 0) {
        int old = atomicAdd(&d_ticket[2], 1);
        s_last = (old == (int)gridDim.x - 1);
        if (s_last) d_ticket[2] = 0;
    }
    __syncthreads();
    if (s_last) {
        __threadfence();
        float sm2 = 0.f, q2 = 0.f;
        for (int b = sl; b < (int)gridDim.x; b += 2) {
            sm2 += d_psum[b * 128 + c];
            q2  += d_psq [b * 128 + c];
        }
        __syncthreads();
        if (sl == 1) { s0[c] = sm2; q0[c] = q2; }
        __syncthreads();
        if (sl == 0) {
            float S = sm2 + s0[c];
            float Q = q2  + q0[c];
            float m = S / (float)N_NODES;
            float v = Q / (float)N_NODES - m * m;
            float a = g[c] * rsqrtf(v + BN_EPS);
            scale[c] = a;
            shift[c] = be[c] - m * a;
        }
    }
}

// ----------------------------- final elementwise (float4) ------------------
__global__ void final_kernel(float4* __restrict__ out4) {
    int i = blockIdx.x * blockDim.x + threadIdx.x;   // 0 .. 1.6M-1
    if (i >= N_NODES * 32) return;
    if (i < N_NODES) d_cnt[i] = 0;                   // prep next graph replay
    int c = (i & 31) * 4;
    float4 v = reinterpret_cast<const float4*>(d_Y2)[i];
    float4 o;
    o.x = fmaf(d_scale3[c+0], fmaxf(fmaf(d_scale2[c+0], v.x, d_shift2[c+0]), 0.f), d_shift3[c+0]);
    o.y = fmaf(d_scale3[c+1], fmaxf(fmaf(d_scale2[c+1], v.y, d_shift2[c+1]), 0.f), d_shift3[c+1]);
    o.z = fmaf(d_scale3[c+2], fmaxf(fmaf(d_scale2[c+2], v.z, d_shift2[c+2]), 0.f), d_shift3[c+2]);
    o.w = fmaf(d_scale3[c+3], fmaxf(fmaf(d_scale2[c+3], v.w, d_shift2[c+3]), 0.f), d_shift3[c+3]);
    out4[i] = o;
}

// ---------------------------------------------------------------------------
extern "C" void kernel_launch(void* const* d_in, const int* in_sizes, int n_in,
                              void* d_out, int out_size) {
    const float* feats = (const float*)d_in[0];
    const int*   src   = (const int*)  d_in[1];
    const int*   dst   = (const int*)  d_in[2];
    const float* W1    = (const float*)d_in[3];
    const float* b1    = (const float*)d_in[4];
    const float* g1    = (const float*)d_in[5];
    const float* be1   = (const float*)d_in[6];
    const float* W2    = (const float*)d_in[7];
    const float* b2    = (const float*)d_in[8];
    const float* g2    = (const float*)d_in[9];
    const float* be2   = (const float*)d_in[10];
    const float* g3    = (const float*)d_in[11];
    const float* be3   = (const float*)d_in[12];
    float* out = (float*)d_out;

    static bool attr_set = false;
    const int GEMM_SMEM = 2 * 128 * 128 * sizeof(float);  // 128 KB
    if (!attr_set) {
        cudaFuncSetAttribute(gemm_kernel,
                             cudaFuncAttributeMaxDynamicSharedMemorySize,
                             GEMM_SMEM);
        attr_set = true;
    }

    float *s1, *t1, *s2, *t2, *s3, *t3;
    cudaGetSymbolAddress((void**)&s1, d_scale1);
    cudaGetSymbolAddress((void**)&t1, d_shift1);
    cudaGetSymbolAddress((void**)&s2, d_scale2);
    cudaGetSymbolAddress((void**)&t2, d_shift2);
    cudaGetSymbolAddress((void**)&s3, d_scale3);
    cudaGetSymbolAddress((void**)&t3, d_shift3);
    float *H, *Y1, *Y2;
    cudaGetSymbolAddress((void**)&H,  d_H);
    cudaGetSymbolAddress((void**)&Y1, d_Y1);
    cudaGetSymbolAddress((void**)&Y2, d_Y2);

    scatter_kernel<<<(N_EDGES + 255) / 256, 256>>>(src, dst);
    aggregate_kernel<<<(N_NODES * 32 + 255) / 256, 256>>>(feats, src, dst);

    // Y1 = H @ W1 + b1   (+ fused stats + finalize -> scale1/shift1)
    gemm_kernel<<<NBLK_GEMM, 512, GEMM_SMEM>>>(H, W1, b1, Y1,
                                               nullptr, nullptr,
                                               g1, be1, s1, t1, 0);
    // Y2 = relu(BN(Y1)) @ W2 + b2  (+ fused stats + finalize -> scale2/shift2)
    gemm_kernel<<<NBLK_GEMM, 512, GEMM_SMEM>>>(Y1, W2, b2, Y2,
                                               s1, t1,
                                               g2, be2, s2, t2, 1);
    // stats of h2 = relu(BN(Y2))  (+ fused finalize -> scale3/shift3)
    colreduce_kernel<<<NBLK_RED, 256>>>(Y2, s2, t2, g3, be3, s3, t3);
    // out = BN3(relu(BN2(Y2)))  (+ re-zero d_cnt)
    final_kernel<<<(N_NODES * 32 + 255) / 256, 256>>>(
        reinterpret_cast<float4*>(out));
}